// round 8
// baseline (speedup 1.0000x reference)
#include <cuda_runtime.h>
#include <math.h>

#define TT 2048
#define WDIM 768
#define HH 512
#define G4 2048      // 4*H
#define NCAT 5
#define STARTT 3
#define ENDT 4
#define NCB 64       // CTAs in fused bidirectional recurrence
#define CELLS 8      // h cells per CTA per direction
#define RPC 32       // gate rows per CTA per direction

// -------- scratch (static device globals; no allocation) --------
__device__ float Zbuf[2][(size_t)TT * G4];      // z_in per direction (32 MB)
__device__ float Hcat[(size_t)TT * 2 * HH];     // [t][h_f | h_b] (8 MB)
__device__ float hbuf[2][2][HH];                // [dir][phase][H] ping-pong
__device__ int   flagv[NCB];                    // monotonic step stamps per CTA
__device__ float feats_g[TT * NCAT];

// ================= helpers =================
__device__ __forceinline__ unsigned long long pack2(float x, float y) {
    unsigned long long r;
    asm("mov.b64 %0, {%1, %2};" : "=l"(r) : "f"(x), "f"(y));
    return r;
}
__device__ __forceinline__ void ffma2(unsigned long long& acc,
                                      unsigned long long a, unsigned long long b) {
    asm("fma.rn.f32x2 %0, %1, %2, %0;" : "+l"(acc) : "l"(a), "l"(b));
}
// EXACT numerics (validated: rel_err 1.6e-5 in R1/R2)
__device__ __forceinline__ float sigm(float x) { return 1.f / (1.f + expf(-x)); }

// ================= zero flags (per graph replay) =================
__global__ void zero_state() {
    int i = threadIdx.x;
    if (i < NCB) flagv[i] = 0;
}

// ================= Kernel A: gather + z_in GEMM =================
#define BM 128
#define BN 128
#define BK 16

__global__ __launch_bounds__(256, 1) void gemm_zin(
    const int* __restrict__ sent, const float* __restrict__ emb,
    const float* __restrict__ WihF, const float* __restrict__ WihB,
    const float* __restrict__ bihF, const float* __restrict__ bhhF,
    const float* __restrict__ bihB, const float* __restrict__ bhhB)
{
    const int dir = blockIdx.z;
    const float* __restrict__ Wih = dir ? WihB : WihF;
    const float* __restrict__ b1  = dir ? bihB : bihF;
    const float* __restrict__ b2  = dir ? bhhB : bhhF;
    float* __restrict__ Z = Zbuf[dir];

    __shared__ float As[BK][BM + 4];
    __shared__ float Bs[BK][BN + 4];
    __shared__ int   sidx[BM];

    const int tid = threadIdx.x;
    const int m0 = blockIdx.y * BM;
    const int n0 = blockIdx.x * BN;

    if (tid < BM) sidx[tid] = sent[m0 + tid];
    __syncthreads();

    const int la_r = tid >> 2;
    const int la_k = (tid & 3) * 4;
    const int tx = tid & 15, ty = tid >> 4;

    float acc[8][8];
    #pragma unroll
    for (int i = 0; i < 8; i++)
        #pragma unroll
        for (int j = 0; j < 8; j++) acc[i][j] = 0.f;

    for (int k0 = 0; k0 < WDIM; k0 += BK) {
        #pragma unroll
        for (int i = 0; i < 2; i++) {
            int m = la_r + i * 64;
            float4 v = *reinterpret_cast<const float4*>(
                &emb[(size_t)sidx[m] * WDIM + k0 + la_k]);
            As[la_k + 0][m] = v.x; As[la_k + 1][m] = v.y;
            As[la_k + 2][m] = v.z; As[la_k + 3][m] = v.w;
        }
        #pragma unroll
        for (int i = 0; i < 2; i++) {
            int n = la_r + i * 64;
            float4 v = *reinterpret_cast<const float4*>(
                &Wih[(size_t)(n0 + n) * WDIM + k0 + la_k]);
            Bs[la_k + 0][n] = v.x; Bs[la_k + 1][n] = v.y;
            Bs[la_k + 2][n] = v.z; Bs[la_k + 3][n] = v.w;
        }
        __syncthreads();

        #pragma unroll
        for (int k = 0; k < BK; k++) {
            float a[8], b[8];
            float4 a0 = *reinterpret_cast<const float4*>(&As[k][ty * 8]);
            float4 a1 = *reinterpret_cast<const float4*>(&As[k][ty * 8 + 4]);
            float4 b0 = *reinterpret_cast<const float4*>(&Bs[k][tx * 8]);
            float4 b1v = *reinterpret_cast<const float4*>(&Bs[k][tx * 8 + 4]);
            a[0]=a0.x; a[1]=a0.y; a[2]=a0.z; a[3]=a0.w;
            a[4]=a1.x; a[5]=a1.y; a[6]=a1.z; a[7]=a1.w;
            b[0]=b0.x; b[1]=b0.y; b[2]=b0.z; b[3]=b0.w;
            b[4]=b1v.x; b[5]=b1v.y; b[6]=b1v.z; b[7]=b1v.w;
            #pragma unroll
            for (int i = 0; i < 8; i++)
                #pragma unroll
                for (int j = 0; j < 8; j++)
                    acc[i][j] = fmaf(a[i], b[j], acc[i][j]);
        }
        __syncthreads();
    }

    #pragma unroll
    for (int i = 0; i < 8; i++) {
        int m = m0 + ty * 8 + i;
        #pragma unroll
        for (int j = 0; j < 8; j++) {
            int n = n0 + tx * 8 + j;
            Z[(size_t)m * G4 + n] = acc[i][j] + b1[n] + b2[n];
        }
    }
}

// ================= Kernel B: fused bidirectional LSTM recurrence =================
// 64 CTAs x 256 threads. CTA k owns h cells [k*8, k*8+8) for BOTH directions.
// Sync protocol uses the SAME memory-op types as the validated R2 kernel:
//   release: tid0 __threadfence() then VOLATILE flag store (monotonic s+1)
//   poll:    64 threads spin on VOLATILE loads (no barrier inside loop)
//   acquire: __syncthreads() + __threadfence(), then __ldcg reload of h.
// (Weak ld.cg/st.cg in the sync path was the R4-R6 corruption source.)
__global__ __launch_bounds__(256, 1) void lstm_rec(
    const float* __restrict__ WhhF, const float* __restrict__ WhhB)
{
    const int k = blockIdx.x;
    const int tid = threadIdx.x;
    const int row = tid >> 3;       // 0..31
    const int sub = tid & 7;
    const int gate = row >> 3;
    const int j = row & 7;
    const int grow = gate * HH + k * CELLS + j;

    __shared__ __align__(16) float hs[2][HH];
    __shared__ float garr[2][RPC];
    __shared__ float c_s[2][CELLS];

    // Whh slices in registers, packed f32x2, both directions
    unsigned long long w2[2][32];
    #pragma unroll
    for (int d = 0; d < 2; d++) {
        const float* __restrict__ W = d ? WhhB : WhhF;
        const float* wr = &W[(size_t)grow * HH];
        #pragma unroll
        for (int c = 0; c < 16; c++) {
            float4 v = *reinterpret_cast<const float4*>(&wr[c * 32 + sub * 4]);
            w2[d][2 * c]     = pack2(v.x, v.y);
            w2[d][2 * c + 1] = pack2(v.z, v.w);
        }
    }

    for (int i = tid; i < 2 * HH; i += 256) ((float*)hs)[i] = 0.f;
    if (tid < 16) c_s[tid >> 3][tid & 7] = 0.f;

    float zcur0 = 0.f, zcur1 = 0.f, znx0 = 0.f, znx1 = 0.f;
    if (sub == 0) {
        zcur0 = __ldg(&Zbuf[0][grow]);
        zcur1 = __ldg(&Zbuf[1][(size_t)(TT - 1) * G4 + grow]);
    }
    __syncthreads();

    for (int s = 0; s < TT; s++) {
        // prefetch next step's z
        const int sp = (s + 1 < TT) ? s + 1 : s;
        if (sub == 0) {
            znx0 = __ldg(&Zbuf[0][(size_t)sp * G4 + grow]);
            znx1 = __ldg(&Zbuf[1][(size_t)(TT - 1 - sp) * G4 + grow]);
        }

        // gate matvec, both directions
        #pragma unroll
        for (int d = 0; d < 2; d++) {
            unsigned long long a0 = 0ull, a1 = 0ull;
            #pragma unroll
            for (int c = 0; c < 16; c++) {
                ulonglong2 hh = *reinterpret_cast<const ulonglong2*>(
                    &hs[d][c * 32 + sub * 4]);
                ffma2(a0, w2[d][2 * c],     hh.x);
                ffma2(a1, w2[d][2 * c + 1], hh.y);
            }
            float2 fa = *(float2*)&a0;
            float2 fb = *(float2*)&a1;
            float acc = (fa.x + fa.y) + (fb.x + fb.y);
            acc += __shfl_xor_sync(0xffffffffu, acc, 4);
            acc += __shfl_xor_sync(0xffffffffu, acc, 2);
            acc += __shfl_xor_sync(0xffffffffu, acc, 1);
            if (sub == 0) garr[d][row] = acc + (d ? zcur1 : zcur0);
        }
        __syncthreads();

        // cell update: 16 threads (8 cells x 2 dirs), exact math
        if (tid < 16) {
            const int d = tid >> 3, cell = tid & 7;
            float gi = garr[d][cell],      gf = garr[d][8 + cell],
                  gg = garr[d][16 + cell], go = garr[d][24 + cell];
            float c = sigm(gf) * c_s[d][cell] + sigm(gi) * tanhf(gg);
            c_s[d][cell] = c;
            float h = sigm(go) * tanhf(c);
            const int t = d ? (TT - 1 - s) : s;
            Hcat[(size_t)t * (2 * HH) + d * HH + k * CELLS + cell] = h;
            __stcg(&hbuf[d][s & 1][k * CELLS + cell], h);
        }
        __syncthreads();
        if (s == TT - 1) break;

        // release: fence + VOLATILE monotonic flag store (single writer)
        if (tid == 0) {
            __threadfence();
            ((volatile int*)flagv)[k] = s + 1;
        }

        // barrier-free poll on monotonic flags (VOLATILE loads)
        if (tid < NCB) {
            const int want = s + 1;
            while (((volatile int*)flagv)[tid] < want) { }
        }
        __syncthreads();
        __threadfence();   // acquire

        // cooperative reload of h: 1024 floats, float4 per thread
        {
            const int dd = tid >> 7;
            const int e = (tid & 127) * 4;
            float4 v = __ldcg(reinterpret_cast<const float4*>(&hbuf[dd][s & 1][e]));
            *reinterpret_cast<float4*>(&hs[dd][e]) = v;
        }
        zcur0 = znx0; zcur1 = znx1;
        __syncthreads();
    }
}

// ================= Kernel C: FC feats =================
__global__ __launch_bounds__(256) void fc_feats(
    const float* __restrict__ fc_w, const float* __restrict__ fc_b)
{
    __shared__ float wsh[NCAT][2 * HH];
    for (int i = threadIdx.x; i < NCAT * 2 * HH; i += 256)
        wsh[i / (2 * HH)][i % (2 * HH)] = fc_w[i];
    __syncthreads();

    const int warp = threadIdx.x >> 5, lane = threadIdx.x & 31;
    const int t = blockIdx.x * 8 + warp;

    float a[NCAT];
    #pragma unroll
    for (int c = 0; c < NCAT; c++) a[c] = 0.f;
    for (int e = lane; e < 2 * HH; e += 32) {
        float x = Hcat[(size_t)t * 2 * HH + e];
        #pragma unroll
        for (int c = 0; c < NCAT; c++) a[c] = fmaf(x, wsh[c][e], a[c]);
    }
    #pragma unroll
    for (int c = 0; c < NCAT; c++) {
        #pragma unroll
        for (int o = 16; o > 0; o >>= 1)
            a[c] += __shfl_xor_sync(0xffffffffu, a[c], o);
    }
    if (lane == 0) {
        #pragma unroll
        for (int c = 0; c < NCAT; c++)
            feats_g[t * NCAT + c] = a[c] + fc_b[c];
    }
}

// ================= Kernel D: Viterbi + backtrack + output =================
__global__ __launch_bounds__(32) void viterbi(
    const float* __restrict__ trans, float* __restrict__ out)
{
    __shared__ int par[(TT - 1) * NCAT];
    const int tid = threadIdx.x;

    float trow[NCAT];
    float layer = 0.f;
    if (tid < NCAT) {
        #pragma unroll
        for (int jj = 0; jj < NCAT; jj++) trow[jj] = trans[tid * NCAT + jj];
        layer = feats_g[tid] + trans[tid * NCAT + STARTT];
    }

    for (int t = 1; t < TT; t++) {
        float lj[NCAT];
        #pragma unroll
        for (int jj = 0; jj < NCAT; jj++)
            lj[jj] = __shfl_sync(0xffffffffu, layer, jj);
        if (tid < NCAT) {
            float best = trow[0] + lj[0];
            int barg = 0;
            #pragma unroll
            for (int jj = 1; jj < NCAT; jj++) {
                float sc = trow[jj] + lj[jj];
                if (sc > best) { best = sc; barg = jj; }
            }
            layer = best + feats_g[t * NCAT + tid];
            par[(t - 1) * NCAT + tid] = barg;
        }
    }

    __shared__ float finsh[NCAT];
    if (tid < NCAT) finsh[tid] = layer + trans[ENDT * NCAT + tid];
    __syncthreads();

    if (tid == 0) {
        int idx = 0; float best = finsh[0];
        #pragma unroll
        for (int i = 1; i < NCAT; i++)
            if (finsh[i] > best) { best = finsh[i]; idx = i; }
        out[TT] = best;
        out[TT - 1] = (float)idx;
        for (int t = TT - 2; t >= 0; t--) {
            idx = par[t * NCAT + idx];
            out[t] = (float)idx;
        }
    }
}

// ================= launch =================
extern "C" void kernel_launch(void* const* d_in, const int* in_sizes, int n_in,
                              void* d_out, int out_size)
{
    const int*   sent  = (const int*)d_in[0];
    const float* emb   = (const float*)d_in[1];
    const float* WihF  = (const float*)d_in[2];
    const float* WhhF  = (const float*)d_in[3];
    const float* bihF  = (const float*)d_in[4];
    const float* bhhF  = (const float*)d_in[5];
    const float* WihB  = (const float*)d_in[6];
    const float* WhhB  = (const float*)d_in[7];
    const float* bihB  = (const float*)d_in[8];
    const float* bhhB  = (const float*)d_in[9];
    const float* fc_w  = (const float*)d_in[10];
    const float* fc_b  = (const float*)d_in[11];
    const float* trans = (const float*)d_in[12];
    float* out = (float*)d_out;

    zero_state<<<1, 64>>>();

    dim3 g(G4 / BN, TT / BM, 2);
    gemm_zin<<<g, 256>>>(sent, emb, WihF, WihB, bihF, bhhF, bihB, bhhB);

    lstm_rec<<<NCB, 256>>>(WhhF, WhhB);

    fc_feats<<<TT / 8, 256>>>(fc_w, fc_b);

    viterbi<<<1, 32>>>(trans, out);
}

// round 9
// speedup vs baseline: 1.8406x; 1.8406x over previous
#include <cuda_runtime.h>
#include <math.h>

#define TT 2048
#define WDIM 768
#define HH 512
#define G4 2048      // 4*H
#define NCAT 5
#define STARTT 3
#define ENDT 4
#define NCB 64       // CTAs in fused bidirectional recurrence
#define CELLS 8      // h cells per CTA per direction
#define RPC 32       // gate rows per CTA per direction

// -------- scratch (static device globals; no allocation) --------
__device__ float Zbuf[2][(size_t)TT * G4];      // z_in per direction (32 MB)
__device__ float Hcat[(size_t)TT * 2 * HH];     // [t][h_f | h_b] (8 MB)
__device__ float hbuf[2][2][HH];                // [dir][phase][H] ping-pong
__device__ int   stepcnt[TT];                   // per-step arrival counters
__device__ float feats_g[TT * NCAT];

// ================= helpers =================
__device__ __forceinline__ unsigned long long pack2(float x, float y) {
    unsigned long long r;
    asm("mov.b64 %0, {%1, %2};" : "=l"(r) : "f"(x), "f"(y));
    return r;
}
__device__ __forceinline__ void ffma2(unsigned long long& acc,
                                      unsigned long long a, unsigned long long b) {
    asm("fma.rn.f32x2 %0, %1, %2, %0;" : "+l"(acc) : "l"(a), "l"(b));
}
// EXACT numerics (validated: rel_err 1.6e-5)
__device__ __forceinline__ float sigm(float x) { return 1.f / (1.f + expf(-x)); }

// GPU-scope release/acquire pair — the grid_sync pattern.
// release red: cumulative, orders this CTA's prior (weak) h stores.
// acquire ld:  synchronizes-with the release; following __syncthreads spreads
// the happens-before to all threads' subsequent h loads.
__device__ __forceinline__ void red_release_add1(int* p) {
    asm volatile("red.release.gpu.global.add.u32 [%0], 1;" :: "l"(p) : "memory");
}
__device__ __forceinline__ int ld_acquire(const int* p) {
    int v;
    asm volatile("ld.acquire.gpu.global.u32 %0, [%1];" : "=r"(v) : "l"(p) : "memory");
    return v;
}

// ================= zero counters (per graph replay) =================
__global__ void zero_state() {
    int i = blockIdx.x * blockDim.x + threadIdx.x;
    if (i < TT) stepcnt[i] = 0;
}

// ================= Kernel A: gather + z_in GEMM =================
#define BM 128
#define BN 128
#define BK 16

__global__ __launch_bounds__(256, 1) void gemm_zin(
    const int* __restrict__ sent, const float* __restrict__ emb,
    const float* __restrict__ WihF, const float* __restrict__ WihB,
    const float* __restrict__ bihF, const float* __restrict__ bhhF,
    const float* __restrict__ bihB, const float* __restrict__ bhhB)
{
    const int dir = blockIdx.z;
    const float* __restrict__ Wih = dir ? WihB : WihF;
    const float* __restrict__ b1  = dir ? bihB : bihF;
    const float* __restrict__ b2  = dir ? bhhB : bhhF;
    float* __restrict__ Z = Zbuf[dir];

    __shared__ float As[BK][BM + 4];
    __shared__ float Bs[BK][BN + 4];
    __shared__ int   sidx[BM];

    const int tid = threadIdx.x;
    const int m0 = blockIdx.y * BM;
    const int n0 = blockIdx.x * BN;

    if (tid < BM) sidx[tid] = sent[m0 + tid];
    __syncthreads();

    const int la_r = tid >> 2;
    const int la_k = (tid & 3) * 4;
    const int tx = tid & 15, ty = tid >> 4;

    float acc[8][8];
    #pragma unroll
    for (int i = 0; i < 8; i++)
        #pragma unroll
        for (int j = 0; j < 8; j++) acc[i][j] = 0.f;

    for (int k0 = 0; k0 < WDIM; k0 += BK) {
        #pragma unroll
        for (int i = 0; i < 2; i++) {
            int m = la_r + i * 64;
            float4 v = *reinterpret_cast<const float4*>(
                &emb[(size_t)sidx[m] * WDIM + k0 + la_k]);
            As[la_k + 0][m] = v.x; As[la_k + 1][m] = v.y;
            As[la_k + 2][m] = v.z; As[la_k + 3][m] = v.w;
        }
        #pragma unroll
        for (int i = 0; i < 2; i++) {
            int n = la_r + i * 64;
            float4 v = *reinterpret_cast<const float4*>(
                &Wih[(size_t)(n0 + n) * WDIM + k0 + la_k]);
            Bs[la_k + 0][n] = v.x; Bs[la_k + 1][n] = v.y;
            Bs[la_k + 2][n] = v.z; Bs[la_k + 3][n] = v.w;
        }
        __syncthreads();

        #pragma unroll
        for (int k = 0; k < BK; k++) {
            float a[8], b[8];
            float4 a0 = *reinterpret_cast<const float4*>(&As[k][ty * 8]);
            float4 a1 = *reinterpret_cast<const float4*>(&As[k][ty * 8 + 4]);
            float4 b0 = *reinterpret_cast<const float4*>(&Bs[k][tx * 8]);
            float4 b1v = *reinterpret_cast<const float4*>(&Bs[k][tx * 8 + 4]);
            a[0]=a0.x; a[1]=a0.y; a[2]=a0.z; a[3]=a0.w;
            a[4]=a1.x; a[5]=a1.y; a[6]=a1.z; a[7]=a1.w;
            b[0]=b0.x; b[1]=b0.y; b[2]=b0.z; b[3]=b0.w;
            b[4]=b1v.x; b[5]=b1v.y; b[6]=b1v.z; b[7]=b1v.w;
            #pragma unroll
            for (int i = 0; i < 8; i++)
                #pragma unroll
                for (int j = 0; j < 8; j++)
                    acc[i][j] = fmaf(a[i], b[j], acc[i][j]);
        }
        __syncthreads();
    }

    #pragma unroll
    for (int i = 0; i < 8; i++) {
        int m = m0 + ty * 8 + i;
        #pragma unroll
        for (int j = 0; j < 8; j++) {
            int n = n0 + tx * 8 + j;
            Z[(size_t)m * G4 + n] = acc[i][j] + b1[n] + b2[n];
        }
    }
}

// ================= Kernel B: fused bidirectional LSTM recurrence =================
// 64 CTAs x 256 threads. CTA k owns h cells [k*8, k*8+8) for BOTH directions.
// Per-step grid sync: tid0 red.release.gpu.add(stepcnt[s]); tid0 spins on
// ld.acquire.gpu until == NCB; __syncthreads; reload h (ping-pong buffers).
__global__ __launch_bounds__(256, 1) void lstm_rec(
    const float* __restrict__ WhhF, const float* __restrict__ WhhB)
{
    const int k = blockIdx.x;
    const int tid = threadIdx.x;
    const int row = tid >> 3;       // 0..31
    const int sub = tid & 7;
    const int gate = row >> 3;
    const int j = row & 7;
    const int grow = gate * HH + k * CELLS + j;

    __shared__ __align__(16) float hs[2][HH];
    __shared__ float garr[2][RPC];
    __shared__ float c_s[2][CELLS];

    // Whh slices in registers, packed f32x2, both directions
    unsigned long long w2[2][32];
    #pragma unroll
    for (int d = 0; d < 2; d++) {
        const float* __restrict__ W = d ? WhhB : WhhF;
        const float* wr = &W[(size_t)grow * HH];
        #pragma unroll
        for (int c = 0; c < 16; c++) {
            float4 v = *reinterpret_cast<const float4*>(&wr[c * 32 + sub * 4]);
            w2[d][2 * c]     = pack2(v.x, v.y);
            w2[d][2 * c + 1] = pack2(v.z, v.w);
        }
    }

    for (int i = tid; i < 2 * HH; i += 256) ((float*)hs)[i] = 0.f;
    if (tid < 16) c_s[tid >> 3][tid & 7] = 0.f;

    float zcur0 = 0.f, zcur1 = 0.f, znx0 = 0.f, znx1 = 0.f;
    if (sub == 0) {
        zcur0 = __ldg(&Zbuf[0][grow]);
        zcur1 = __ldg(&Zbuf[1][(size_t)(TT - 1) * G4 + grow]);
    }
    __syncthreads();

    for (int s = 0; s < TT; s++) {
        // prefetch next step's z
        const int sp = (s + 1 < TT) ? s + 1 : s;
        if (sub == 0) {
            znx0 = __ldg(&Zbuf[0][(size_t)sp * G4 + grow]);
            znx1 = __ldg(&Zbuf[1][(size_t)(TT - 1 - sp) * G4 + grow]);
        }

        // gate matvec, both directions
        #pragma unroll
        for (int d = 0; d < 2; d++) {
            unsigned long long a0 = 0ull, a1 = 0ull;
            #pragma unroll
            for (int c = 0; c < 16; c++) {
                ulonglong2 hh = *reinterpret_cast<const ulonglong2*>(
                    &hs[d][c * 32 + sub * 4]);
                ffma2(a0, w2[d][2 * c],     hh.x);
                ffma2(a1, w2[d][2 * c + 1], hh.y);
            }
            float2 fa = *(float2*)&a0;
            float2 fb = *(float2*)&a1;
            float acc = (fa.x + fa.y) + (fb.x + fb.y);
            acc += __shfl_xor_sync(0xffffffffu, acc, 4);
            acc += __shfl_xor_sync(0xffffffffu, acc, 2);
            acc += __shfl_xor_sync(0xffffffffu, acc, 1);
            if (sub == 0) garr[d][row] = acc + (d ? zcur1 : zcur0);
        }
        __syncthreads();

        // cell update: 16 threads (8 cells x 2 dirs), exact math
        if (tid < 16) {
            const int d = tid >> 3, cell = tid & 7;
            float gi = garr[d][cell],      gf = garr[d][8 + cell],
                  gg = garr[d][16 + cell], go = garr[d][24 + cell];
            float c = sigm(gf) * c_s[d][cell] + sigm(gi) * tanhf(gg);
            c_s[d][cell] = c;
            float h = sigm(go) * tanhf(c);
            const int t = d ? (TT - 1 - s) : s;
            Hcat[(size_t)t * (2 * HH) + d * HH + k * CELLS + cell] = h;
            __stcg(&hbuf[d][s & 1][k * CELLS + cell], h);
        }
        __syncthreads();
        if (s == TT - 1) break;

        // grid sync: release-arrive + acquire-spin (tid0 only), then CTA barrier
        if (tid == 0) {
            red_release_add1(&stepcnt[s]);
            while (ld_acquire(&stepcnt[s]) < NCB) { }
        }
        __syncthreads();

        // cooperative reload of h: 1024 floats, float4 per thread
        {
            const int dd = tid >> 7;
            const int e = (tid & 127) * 4;
            float4 v = __ldcg(reinterpret_cast<const float4*>(&hbuf[dd][s & 1][e]));
            *reinterpret_cast<float4*>(&hs[dd][e]) = v;
        }
        zcur0 = znx0; zcur1 = znx1;
        __syncthreads();
    }
}

// ================= Kernel C: FC feats =================
__global__ __launch_bounds__(256) void fc_feats(
    const float* __restrict__ fc_w, const float* __restrict__ fc_b)
{
    __shared__ float wsh[NCAT][2 * HH];
    for (int i = threadIdx.x; i < NCAT * 2 * HH; i += 256)
        wsh[i / (2 * HH)][i % (2 * HH)] = fc_w[i];
    __syncthreads();

    const int warp = threadIdx.x >> 5, lane = threadIdx.x & 31;
    const int t = blockIdx.x * 8 + warp;

    float a[NCAT];
    #pragma unroll
    for (int c = 0; c < NCAT; c++) a[c] = 0.f;
    for (int e = lane; e < 2 * HH; e += 32) {
        float x = Hcat[(size_t)t * 2 * HH + e];
        #pragma unroll
        for (int c = 0; c < NCAT; c++) a[c] = fmaf(x, wsh[c][e], a[c]);
    }
    #pragma unroll
    for (int c = 0; c < NCAT; c++) {
        #pragma unroll
        for (int o = 16; o > 0; o >>= 1)
            a[c] += __shfl_xor_sync(0xffffffffu, a[c], o);
    }
    if (lane == 0) {
        #pragma unroll
        for (int c = 0; c < NCAT; c++)
            feats_g[t * NCAT + c] = a[c] + fc_b[c];
    }
}

// ================= Kernel D: Viterbi + backtrack + output =================
__global__ __launch_bounds__(32) void viterbi(
    const float* __restrict__ trans, float* __restrict__ out)
{
    __shared__ int par[(TT - 1) * NCAT];
    const int tid = threadIdx.x;

    float trow[NCAT];
    float layer = 0.f;
    if (tid < NCAT) {
        #pragma unroll
        for (int jj = 0; jj < NCAT; jj++) trow[jj] = trans[tid * NCAT + jj];
        layer = feats_g[tid] + trans[tid * NCAT + STARTT];
    }

    for (int t = 1; t < TT; t++) {
        float lj[NCAT];
        #pragma unroll
        for (int jj = 0; jj < NCAT; jj++)
            lj[jj] = __shfl_sync(0xffffffffu, layer, jj);
        if (tid < NCAT) {
            float best = trow[0] + lj[0];
            int barg = 0;
            #pragma unroll
            for (int jj = 1; jj < NCAT; jj++) {
                float sc = trow[jj] + lj[jj];
                if (sc > best) { best = sc; barg = jj; }
            }
            layer = best + feats_g[t * NCAT + tid];
            par[(t - 1) * NCAT + tid] = barg;
        }
    }

    __shared__ float finsh[NCAT];
    if (tid < NCAT) finsh[tid] = layer + trans[ENDT * NCAT + tid];
    __syncthreads();

    if (tid == 0) {
        int idx = 0; float best = finsh[0];
        #pragma unroll
        for (int i = 1; i < NCAT; i++)
            if (finsh[i] > best) { best = finsh[i]; idx = i; }
        out[TT] = best;
        out[TT - 1] = (float)idx;
        for (int t = TT - 2; t >= 0; t--) {
            idx = par[t * NCAT + idx];
            out[t] = (float)idx;
        }
    }
}

// ================= launch =================
extern "C" void kernel_launch(void* const* d_in, const int* in_sizes, int n_in,
                              void* d_out, int out_size)
{
    const int*   sent  = (const int*)d_in[0];
    const float* emb   = (const float*)d_in[1];
    const float* WihF  = (const float*)d_in[2];
    const float* WhhF  = (const float*)d_in[3];
    const float* bihF  = (const float*)d_in[4];
    const float* bhhF  = (const float*)d_in[5];
    const float* WihB  = (const float*)d_in[6];
    const float* WhhB  = (const float*)d_in[7];
    const float* bihB  = (const float*)d_in[8];
    const float* bhhB  = (const float*)d_in[9];
    const float* fc_w  = (const float*)d_in[10];
    const float* fc_b  = (const float*)d_in[11];
    const float* trans = (const float*)d_in[12];
    float* out = (float*)d_out;

    zero_state<<<TT / 256, 256>>>();

    dim3 g(G4 / BN, TT / BM, 2);
    gemm_zin<<<g, 256>>>(sent, emb, WihF, WihB, bihF, bhhF, bihB, bhhB);

    lstm_rec<<<NCB, 256>>>(WhhF, WhhB);

    fc_feats<<<TT / 8, 256>>>(fc_w, fc_b);

    viterbi<<<1, 32>>>(trans, out);
}